// round 16
// baseline (speedup 1.0000x reference)
#include <cuda_runtime.h>

#define BB 4
#define NN 16384
#define NC 1024

// ---------------- scratch (device globals; no allocation allowed) ----------------
__device__ unsigned int g_flagbits[BB][NN / 32];
__device__ int          g_list[BB][NN];
__device__ int          g_list_cnt[BB];
__device__ float        g_feat[BB * 1024];           // max-pooled (relu'd) features
__device__ float        g_a1[BB][512];               // fc layer-1 activations
__device__ float        g_w5t[128 * 1024];           // transposed w5: [k][o]

// ---------------- helpers ----------------
__device__ __forceinline__ unsigned sortable(float d) {
    unsigned u = __float_as_uint(d);
    return (u & 0x80000000u) ? ~u : (u | 0x80000000u);   // ascending-sortable
}

__device__ __forceinline__ float warp_sum(float s) {
    #pragma unroll
    for (int off = 16; off; off >>= 1)
        s += __shfl_xor_sync(0xffffffffu, s, off);
    return s;
}

__device__ __forceinline__ void ffma2(unsigned long long& acc, unsigned long long a,
                                      unsigned long long b) {
    asm("fma.rn.f32x2 %0, %1, %2, %0;" : "+l"(acc) : "l"(a), "l"(b));
}

__device__ __forceinline__ unsigned long long pack2(float lo, float hi) {
    unsigned long long r;
    asm("mov.b64 %0, {%1, %2};" : "=l"(r)
        : "r"(__float_as_uint(lo)), "r"(__float_as_uint(hi)));
    return r;
}

__device__ __forceinline__ unsigned long long add2(unsigned long long a, unsigned long long b) {
    unsigned long long r;
    asm("add.rn.f32x2 %0, %1, %2;" : "=l"(r) : "l"(a), "l"(b));
    return r;
}

__device__ __forceinline__ unsigned long long mul2(unsigned long long a, unsigned long long b) {
    unsigned long long r;
    asm("mul.rn.f32x2 %0, %1, %2;" : "=l"(r) : "l"(a), "l"(b));
    return r;
}

__device__ __forceinline__ void unpack2(unsigned long long v, float& lo, float& hi) {
    unsigned a, b;
    asm("mov.b64 {%0, %1}, %2;" : "=r"(a), "=r"(b) : "l"(v));
    lo = __uint_as_float(a); hi = __uint_as_float(b);
}

// ---------------- prep: w5 transpose (blocks 0-127) + zero (128-159) --------------
__global__ __launch_bounds__(256) void prep_kernel(const float* __restrict__ w5) {
    const int t = threadIdx.x;
    if (blockIdx.x < 128) {
        __shared__ float tile[32][33];
        const int k0 = (blockIdx.x & 3) * 32;
        const int o0 = (blockIdx.x >> 2) * 32;
        const int tx = t & 31, ty = t >> 5;
        #pragma unroll
        for (int r = ty; r < 32; r += 8)
            tile[r][tx] = w5[(o0 + r) * 128 + k0 + tx];     // coalesced read
        __syncthreads();
        #pragma unroll
        for (int r = ty; r < 32; r += 8)
            g_w5t[(k0 + r) * 1024 + o0 + tx] = tile[tx][r]; // coalesced write
    } else {
        int i = (blockIdx.x - 128) * 256 + t;               // 0..8191
        if (i < BB * NN / 32) ((unsigned*)g_flagbits)[i] = 0u;
        if (i < BB * 1024)    g_feat[i] = 0.0f;
        if (i < BB)           g_list_cnt[i] = 0;
    }
}

// ---------------- fused FPS walk + exact radix top-32 KNN + dedup append ----------
// BB*32 blocks of 1024; all co-resident. float4-coalesced staging; packed walk.
__global__ __launch_bounds__(1024) void fpsknn_kernel(const float* __restrict__ x,
                                                      const int* __restrict__ far_init) {
    extern __shared__ float dsm[];
    float* sx = dsm;
    float* sy = sx + NN;
    float* sz = sy + NN;
    unsigned long long* cand = (unsigned long long*)(sz + NN);
    __shared__ unsigned s_du[2][32];
    __shared__ unsigned s_iu[2][32];
    __shared__ int s_cent[NC];
    __shared__ int s_stop;
    __shared__ unsigned s_minidx;

    const int b = blockIdx.x >> 5, m0 = blockIdx.x & 31;
    const float* xb = x + (size_t)b * NN * 3;
    const int t = threadIdx.x, w = t >> 5, lane = t & 31;
    const unsigned lmask_lt = (1u << lane) - 1u;

    // ---- coalesced float4 staging into smem SoA ----
    {
        const float4* xb4 = (const float4*)xb;          // 12288 float4 per batch
        #pragma unroll
        for (int j = 0; j < 12; ++j) {
            const int vi = t + j * 1024;
            float4 v = xb4[vi];
            const int e0 = vi * 4;
            float vv[4] = {v.x, v.y, v.z, v.w};
            #pragma unroll
            for (int e = 0; e < 4; ++e) {
                const int idx = e0 + e;
                const int p = idx / 3, c = idx - 3 * p;
                if (c == 0) sx[p] = vv[e];
                else if (c == 1) sy[p] = vv[e];
                else sz[p] = vv[e];
            }
        }
    }
    if (t == 0) s_stop = 0;
    __syncthreads();

    // refill walk registers from smem (conflict-free)
    unsigned long long prx[8], pry[8], prz[8];
    #pragma unroll
    for (int j = 0; j < 8; ++j) {
        const int i0 = t + (2 * j) * 1024, i1 = t + (2 * j + 1) * 1024;
        prx[j] = pack2(sx[i0], sx[i1]);
        pry[j] = pack2(sy[i0], sy[i1]);
        prz[j] = pack2(sz[i0], sz[i1]);
    }

    // ---- FPS walk: packed distances, per-thread seen bits, 1 BAR/iter ----
    int far = far_init[b];
    int cnt = 0;
    unsigned myseen = 0;                 // thread t owns points t + j*1024 (bit j)
    for (int it = 0; it < NC; ++it) {
        if (t == (far & 1023)) {         // owner thread: cycle check + append
            const unsigned bt2 = 1u << (far >> 10);
            if (myseen & bt2) s_stop = 1;
            else { myseen |= bt2; s_cent[cnt] = far; }
        }
        const int pb = it & 1;
        const float cx = sx[far], cy = sy[far], cz = sz[far];
        const unsigned long long ncx = pack2(-cx, -cx);
        const unsigned long long ncy = pack2(-cy, -cy);
        const unsigned long long ncz = pack2(-cz, -cz);

        float best = -1.0f; int bi = 0;
        #pragma unroll
        for (int j = 0; j < 8; ++j) {
            unsigned long long dx2 = add2(prx[j], ncx);
            unsigned long long dy2 = add2(pry[j], ncy);
            unsigned long long dz2 = add2(prz[j], ncz);
            unsigned long long dd = mul2(dx2, dx2);
            ffma2(dd, dy2, dy2);
            ffma2(dd, dz2, dz2);
            float d0, d1; unpack2(dd, d0, d1);
            if (d0 > best) { best = d0; bi = t + (2 * j) * 1024; }       // ascending idx
            if (d1 > best) { best = d1; bi = t + (2 * j + 1) * 1024; }   // order preserved
        }
        const unsigned db = __float_as_uint(best);
        const unsigned dmax = __reduce_max_sync(0xffffffffu, db);
        const unsigned im = (db == dmax) ? (unsigned)bi : 0xffffffffu;
        const unsigned imin = __reduce_min_sync(0xffffffffu, im);
        if (lane == 0) { s_du[pb][w] = dmax; s_iu[pb][w] = imin; }
        __syncthreads();                 // publishes s_stop, s_du/s_iu
        if (s_stop) break;
        cnt++;
        if (it == NC - 1) break;
        const unsigned d2v = s_du[pb][lane];
        const unsigned i2v = s_iu[pb][lane];
        const unsigned dm2 = __reduce_max_sync(0xffffffffu, d2v);
        const unsigned ii = (d2v == dm2) ? i2v : 0xffffffffu;
        far = (int)__reduce_min_sync(0xffffffffu, ii);
    }
    __syncthreads();

    // ---- exact top-32 KNN via two-level radix select ----
    for (int m = m0; m < cnt; m += 32) {
        const int ci = s_cent[m];
        const float cx = sx[ci], cy = sy[ci], cz = sz[ci];
        const float cn = cx * cx + cy * cy + cz * cz;
        const int base = w * 512;

        unsigned ds[16];
        #pragma unroll
        for (int j = 0; j < 16; ++j) {
            const int p = base + j * 32 + lane;
            float px = sx[p], py = sy[p], pz = sz[p];
            float xn = px * px + py * py + pz * pz;
            float dot = cx * px + cy * py + cz * pz;
            ds[j] = sortable((cn + xn) - 2.0f * dot);
        }

        unsigned pfx = 0; int kth = 32;
        for (int bit = 31; bit >= 0; --bit) {
            const unsigned tgt = pfx << 1;
            int c = 0;
            #pragma unroll
            for (int j = 0; j < 16; ++j) c += ((ds[j] >> bit) == tgt);
            const int tot = __reduce_add_sync(0xffffffffu, c);
            if (kth <= tot) pfx = tgt; else { kth -= tot; pfx = tgt + 1; }
        }
        const unsigned T = pfx;

        unsigned selbits = 0;
        int cl = 0;
        #pragma unroll
        for (int j = 0; j < 16; ++j) {
            if (ds[j] < T) { selbits |= 1u << j; ++cl; }
        }
        int mtake = 32 - __reduce_add_sync(0xffffffffu, cl);
        while (mtake > 0) {
            unsigned me = 0xffffffffu; int jmin = -1;
            #pragma unroll
            for (int j = 0; j < 16; ++j) {
                if (ds[j] == T && !((selbits >> j) & 1u)) {
                    unsigned pid = (unsigned)(base + j * 32 + lane);
                    if (pid < me) { me = pid; jmin = j; }
                }
            }
            const unsigned gmin = __reduce_min_sync(0xffffffffu, me);
            if (me == gmin && jmin >= 0) selbits |= 1u << jmin;
            --mtake;
        }

        int off = 0;
        #pragma unroll
        for (int j = 0; j < 16; ++j) {
            const bool s = (selbits >> j) & 1u;
            const unsigned msk = __ballot_sync(0xffffffffu, s);
            if (s) {
                const int pos = off + __popc(msk & lmask_lt);
                cand[w * 32 + pos] = ((unsigned long long)ds[j] << 32)
                                   | (unsigned)(base + j * 32 + lane);
            }
            off += __popc(msk);
        }
        __syncthreads();

        const unsigned long long ck = cand[t];
        const unsigned cd = (unsigned)(ck >> 32);
        const unsigned cidx = (unsigned)ck;
        unsigned qfx = 0; int kb = 32;
        for (int bit = 31; bit >= 0; --bit) {
            const unsigned tgt = qfx << 1;
            const int c1 = __syncthreads_count((cd >> bit) == tgt);
            if (kb <= c1) qfx = tgt; else { kb -= c1; qfx = tgt + 1; }
        }
        const unsigned Tb = qfx;
        const int Lb = __syncthreads_count(cd < Tb);
        int mtk = 32 - Lb;
        bool takeme = (cd < Tb);
        while (mtk > 0) {
            if (t == 0) s_minidx = 0xffffffffu;
            __syncthreads();
            if (cd == Tb && !takeme) atomicMin(&s_minidx, cidx);
            __syncthreads();
            if (cd == Tb && !takeme && cidx == s_minidx) takeme = true;
            --mtk;
            __syncthreads();
        }
        if (takeme) {
            const int n = (int)cidx;
            const unsigned bt2 = 1u << (n & 31);
            unsigned old = atomicOr(&g_flagbits[b][(unsigned)n >> 5], bt2);
            if (!(old & bt2)) {
                int pos = atomicAdd(&g_list_cnt[b], 1);
                g_list[b][pos] = n;
            }
        }
        __syncthreads();
    }
}

// ---------------- fused chain+pool: 32-pt pool passes, all 512 threads ------------
#define PT 32
__global__ __launch_bounds__(512) void poolchain_kernel(
    const float* __restrict__ x,
    const float* __restrict__ w1, const float* __restrict__ b1,
    const float* __restrict__ w2, const float* __restrict__ b2,
    const float* __restrict__ w3, const float* __restrict__ b3,
    const float* __restrict__ w4, const float* __restrict__ b4,
    const float* __restrict__ b5) {
    extern __shared__ float psm[];
    float* hs  = psm;                    // [128][32] k-major, rows 128B
    float* wA  = psm + 128 * PT;         // [64][68]
    float* wB  = wA + 64 * 68;           // [64][68]
    float* wC  = wB + 64 * 68;           // [128][68]
    float* h0  = wC + 128 * 68;          // [16][64]
    float* h1  = h0 + 16 * 64;           // [16][64]
    float* pts = h1 + 16 * 64;           // [32][4]

    const int bid = blockIdx.x;
    const int b = bid >> 5, q = (bid >> 3) & 3, slot = bid & 7;
    const int t = threadIdx.x;
    const int o = t & 63, pg = (t >> 6) & 7;     // 8 groups x 2 points (chain)
    const int p0 = pg * 2, p1 = p0 + 1;

    for (int i = t; i < 64 * 64; i += 512) {
        const int r = i >> 6, c = i & 63;
        wA[r * 68 + c] = w2[i];
        wB[r * 68 + c] = w3[i];
    }
    for (int i = t; i < 128 * 64; i += 512) {
        const int r = i >> 6, c = i & 63;
        wC[r * 68 + c] = w4[i];
    }

    const int cnt = g_list_cnt[b];
    const int half = t >> 8;                     // pool: points half*16..half*16+15
    const int oo = q * 256 + (t & 255);
    const float bias = b5[oo];
    float rmax = 0.0f;

    for (int i0 = slot * PT; i0 < cnt; i0 += 8 * PT) {
        const int rem = min(PT, cnt - i0);
        __syncthreads();                 // weights staged / hs+pts consumed
        if (t < PT) {
            if (t < rem) {
                const int n = g_list[b][i0 + t];
                const float* pp = x + ((size_t)b * NN + n) * 3;
                pts[t * 4 + 0] = pp[0]; pts[t * 4 + 1] = pp[1]; pts[t * 4 + 2] = pp[2];
            } else {
                pts[t * 4 + 0] = 0.f; pts[t * 4 + 1] = 0.f; pts[t * 4 + 2] = 0.f;
            }
        }
        __syncthreads();

        for (int sub = 0; sub < 2; ++sub) {
            const int g0 = sub * 16;
            // L1: 3 -> 64
            {
                const float wa = w1[o * 3 + 0], wb = w1[o * 3 + 1], wc = w1[o * 3 + 2];
                const float bb = b1[o];
                const float* ptA = pts + (g0 + p0) * 4;
                const float* ptB = pts + (g0 + p1) * 4;
                float vA = bb + wa * ptA[0] + wb * ptA[1] + wc * ptA[2];
                float vB = bb + wa * ptB[0] + wb * ptB[1] + wc * ptB[2];
                h0[p0 * 64 + o] = fmaxf(vA, 0.f);
                h0[p1 * 64 + o] = fmaxf(vB, 0.f);
            }
            __syncthreads();
            // L2: 64 -> 64 (wA), h0 -> h1
            {
                const float4* wr = (const float4*)(wA + o * 68);
                const float4* hA = (const float4*)(h0 + p0 * 64);
                const float4* hB = (const float4*)(h0 + p1 * 64);
                float A0=0,A1=0,A2=0,A3=0,B0=0,B1=0,B2=0,B3=0;
                #pragma unroll
                for (int k = 0; k < 16; ++k) {
                    float4 wf = wr[k], ha = hA[k], hb = hB[k];
                    A0 += wf.x * ha.x; A1 += wf.y * ha.y; A2 += wf.z * ha.z; A3 += wf.w * ha.w;
                    B0 += wf.x * hb.x; B1 += wf.y * hb.y; B2 += wf.z * hb.z; B3 += wf.w * hb.w;
                }
                const float bb = b2[o];
                h1[p0 * 64 + o] = fmaxf(bb + ((A0 + A1) + (A2 + A3)), 0.f);
                h1[p1 * 64 + o] = fmaxf(bb + ((B0 + B1) + (B2 + B3)), 0.f);
            }
            __syncthreads();
            // L3: 64 -> 64 (wB), h1 -> h0
            {
                const float4* wr = (const float4*)(wB + o * 68);
                const float4* hA = (const float4*)(h1 + p0 * 64);
                const float4* hB = (const float4*)(h1 + p1 * 64);
                float A0=0,A1=0,A2=0,A3=0,B0=0,B1=0,B2=0,B3=0;
                #pragma unroll
                for (int k = 0; k < 16; ++k) {
                    float4 wf = wr[k], ha = hA[k], hb = hB[k];
                    A0 += wf.x * ha.x; A1 += wf.y * ha.y; A2 += wf.z * ha.z; A3 += wf.w * ha.w;
                    B0 += wf.x * hb.x; B1 += wf.y * hb.y; B2 += wf.z * hb.z; B3 += wf.w * hb.w;
                }
                const float bb = b3[o];
                h0[p0 * 64 + o] = fmaxf(bb + ((A0 + A1) + (A2 + A3)), 0.f);
                h0[p1 * 64 + o] = fmaxf(bb + ((B0 + B1) + (B2 + B3)), 0.f);
            }
            __syncthreads();
            // L4: 64 -> 128 (wC), h0 -> hs[ol][g0 + p]
            {
                #pragma unroll
                for (int j = 0; j < 2; ++j) {
                    const int ol = o + 64 * j;
                    const float4* wr = (const float4*)(wC + ol * 68);
                    const float4* hA = (const float4*)(h0 + p0 * 64);
                    const float4* hB = (const float4*)(h0 + p1 * 64);
                    float A0=0,A1=0,A2=0,A3=0,B0=0,B1=0,B2=0,B3=0;
                    #pragma unroll
                    for (int k = 0; k < 16; ++k) {
                        float4 wf = wr[k], ha = hA[k], hb = hB[k];
                        A0 += wf.x * ha.x; A1 += wf.y * ha.y; A2 += wf.z * ha.z; A3 += wf.w * ha.w;
                        B0 += wf.x * hb.x; B1 += wf.y * hb.y; B2 += wf.z * hb.z; B3 += wf.w * hb.w;
                    }
                    const float bb = b4[ol];
                    hs[ol * PT + g0 + p0] = (g0 + p0 < rem) ? fmaxf(bb + ((A0 + A1) + (A2 + A3)), 0.f) : 0.f;
                    hs[ol * PT + g0 + p1] = (g0 + p1 < rem) ? fmaxf(bb + ((B0 + B1) + (B2 + B3)), 0.f) : 0.f;
                }
            }
            __syncthreads();             // protect h0 reuse / publish hs
        }

        // ---- pool: all 512 threads; thread (half, oo) handles 16 pts ----
        {
            unsigned long long acc2[8];
            #pragma unroll
            for (int pp = 0; pp < 8; ++pp) acc2[pp] = 0ull;

            const float* wtp = g_w5t + oo;
            #pragma unroll 4
            for (int k = 0; k < 128; ++k) {
                const float wv = wtp[k * 1024];
                unsigned long long wv2;
                asm("mov.b64 %0, {%1, %1};" : "=l"(wv2) : "r"(__float_as_uint(wv)));
                const ulonglong2* hp = (const ulonglong2*)(hs + k * PT + half * 16);
                #pragma unroll
                for (int u = 0; u < 4; ++u) {
                    ulonglong2 hv = hp[u];
                    ffma2(acc2[2 * u],     wv2, hv.x);
                    ffma2(acc2[2 * u + 1], wv2, hv.y);
                }
            }
            #pragma unroll
            for (int p = 0; p < 16; ++p) {
                if (half * 16 + p < rem) {
                    const unsigned long long a = acc2[p >> 1];
                    const float av = __uint_as_float((p & 1) ? (unsigned)(a >> 32) : (unsigned)a);
                    rmax = fmaxf(rmax, fmaxf(av + bias, 0.0f));
                }
            }
        }
    }

    atomicMax((unsigned int*)&g_feat[b * 1024 + oo], __float_as_uint(rmax));
}

// ---------------- FC layer 1 (1024->512), one output per warp ---------------------
__global__ __launch_bounds__(256) void fc1_kernel(const float* __restrict__ fw1,
                                                  const float* __restrict__ fb1) {
    const int b = blockIdx.x >> 6, seg = blockIdx.x & 63;
    __shared__ __align__(16) float g[1024];
    const int t = threadIdx.x, w = t >> 5, lane = t & 31;

    for (int i = t; i < 1024; i += 256) g[i] = g_feat[b * 1024 + i];

    const int o = seg * 8 + w;
    const float4* wr = (const float4*)(fw1 + o * 1024);
    float4 wv[8];
    #pragma unroll
    for (int it = 0; it < 8; ++it) wv[it] = wr[it * 32 + lane];   // 8 LDGs in flight

    __syncthreads();
    float s = 0.0f;
    #pragma unroll
    for (int it = 0; it < 8; ++it) {
        float4 gv = *(const float4*)(g + it * 128 + lane * 4);
        s += wv[it].x * gv.x + wv[it].y * gv.y + wv[it].z * gv.z + wv[it].w * gv.w;
    }
    s = warp_sum(s);
    if (lane == 0) g_a1[b][o] = fmaxf(s + fb1[o], 0.0f);
}

// ---------------- FC layers 2+3 (512->256->3), 1 block per batch ------------------
__global__ __launch_bounds__(512) void fc2_kernel(
    const float* __restrict__ fw2, const float* __restrict__ fb2,
    const float* __restrict__ fw3, const float* __restrict__ fb3,
    float* __restrict__ out) {
    const int b = blockIdx.x;
    __shared__ __align__(16) float a1[512];
    __shared__ __align__(16) float a2[256];
    const int t = threadIdx.x, w = t >> 5, lane = t & 31;

    a1[t] = g_a1[b][t];
    __syncthreads();

    {
        const int o = w * 16;
        for (int j = 0; j < 16; ++j) {
            const float4* wr = (const float4*)(fw2 + (o + j) * 512);
            float s = 0.0f;
            #pragma unroll
            for (int it = 0; it < 4; ++it) {
                float4 wv = wr[it * 32 + lane];
                float4 av = *(const float4*)(a1 + it * 128 + lane * 4);
                s += wv.x * av.x + wv.y * av.y + wv.z * av.z + wv.w * av.w;
            }
            s = warp_sum(s);
            if (lane == 0) a2[o + j] = fmaxf(s + fb2[o + j], 0.0f);
        }
    }
    __syncthreads();

    if (w < 3) {
        const float4* wr = (const float4*)(fw3 + w * 256);
        float s = 0.0f;
        #pragma unroll
        for (int it = 0; it < 2; ++it) {
            float4 wv = wr[it * 32 + lane];
            float4 av = *(const float4*)(a2 + it * 128 + lane * 4);
            s += wv.x * av.x + wv.y * av.y + wv.z * av.z + wv.w * av.w;
        }
        s = warp_sum(s);
        if (lane == 0) out[b * 3 + w] = s + fb3[w];
    }
}

// ---------------- launch ----------------
extern "C" void kernel_launch(void* const* d_in, const int* in_sizes, int n_in,
                              void* d_out, int out_size) {
    const float* x   = (const float*)d_in[0];
    const int*   far = (const int*)  d_in[1];
    const float* w1 = (const float*)d_in[2];   const float* b1 = (const float*)d_in[3];
    const float* w2 = (const float*)d_in[4];   const float* b2 = (const float*)d_in[5];
    const float* w3 = (const float*)d_in[6];   const float* b3 = (const float*)d_in[7];
    const float* w4 = (const float*)d_in[8];   const float* b4 = (const float*)d_in[9];
    const float* w5 = (const float*)d_in[10];  const float* b5 = (const float*)d_in[11];
    const float* fw1 = (const float*)d_in[12]; const float* fb1 = (const float*)d_in[13];
    const float* fw2 = (const float*)d_in[14]; const float* fb2 = (const float*)d_in[15];
    const float* fw3 = (const float*)d_in[16]; const float* fb3 = (const float*)d_in[17];
    float* out = (float*)d_out;

    const int smem_fps  = 3 * NN * 4 + 1024 * 8;   // 204800
    const int smem_pool = (128 * PT + 64 * 68 * 2 + 128 * 68 + 16 * 64 * 2 + PT * 4) * 4; // 94720
    static int attr_set = 0;
    if (!attr_set) {
        cudaFuncSetAttribute(fpsknn_kernel,
                             cudaFuncAttributeMaxDynamicSharedMemorySize, smem_fps);
        cudaFuncSetAttribute(poolchain_kernel,
                             cudaFuncAttributeMaxDynamicSharedMemorySize, smem_pool);
        attr_set = 1;
    }

    prep_kernel<<<160, 256>>>(w5);
    fpsknn_kernel<<<BB * 32, 1024, smem_fps>>>(x, far);
    poolchain_kernel<<<BB * 32, 512, smem_pool>>>(x, w1, b1, w2, b2, w3, b3, w4, b4, b5);
    fc1_kernel<<<BB * 64, 256>>>(fw1, fb1);
    fc2_kernel<<<BB, 512>>>(fw2, fb2, fw3, fb3, out);
}

// round 17
// speedup vs baseline: 1.2416x; 1.2416x over previous
#include <cuda_runtime.h>

#define BB 4
#define NN 16384
#define NC 1024

// ---------------- scratch (device globals; no allocation allowed) ----------------
__device__ unsigned int g_flagbits[BB][NN / 32];
__device__ int          g_list[BB][NN];
__device__ int          g_list_cnt[BB];
__device__ float        g_feat[BB * 1024];           // max-pooled (relu'd) features
__device__ float        g_a1[BB][512];               // fc layer-1 activations
__device__ float        g_w5t[128 * 1024];           // transposed w5: [k][o]

// ---------------- helpers ----------------
__device__ __forceinline__ unsigned sortable(float d) {
    unsigned u = __float_as_uint(d);
    return (u & 0x80000000u) ? ~u : (u | 0x80000000u);   // ascending-sortable
}

__device__ __forceinline__ float warp_sum(float s) {
    #pragma unroll
    for (int off = 16; off; off >>= 1)
        s += __shfl_xor_sync(0xffffffffu, s, off);
    return s;
}

__device__ __forceinline__ void ffma2(unsigned long long& acc, unsigned long long a,
                                      unsigned long long b) {
    asm("fma.rn.f32x2 %0, %1, %2, %0;" : "+l"(acc) : "l"(a), "l"(b));
}

__device__ __forceinline__ unsigned long long pack2(float lo, float hi) {
    unsigned long long r;
    asm("mov.b64 %0, {%1, %2};" : "=l"(r)
        : "r"(__float_as_uint(lo)), "r"(__float_as_uint(hi)));
    return r;
}

__device__ __forceinline__ unsigned long long add2(unsigned long long a, unsigned long long b) {
    unsigned long long r;
    asm("add.rn.f32x2 %0, %1, %2;" : "=l"(r) : "l"(a), "l"(b));
    return r;
}

__device__ __forceinline__ unsigned long long mul2(unsigned long long a, unsigned long long b) {
    unsigned long long r;
    asm("mul.rn.f32x2 %0, %1, %2;" : "=l"(r) : "l"(a), "l"(b));
    return r;
}

__device__ __forceinline__ void unpack2(unsigned long long v, float& lo, float& hi) {
    unsigned a, b;
    asm("mov.b64 {%0, %1}, %2;" : "=r"(a), "=r"(b) : "l"(v));
    lo = __uint_as_float(a); hi = __uint_as_float(b);
}

// ---------------- fused FPS walk + exact radix top-32 KNN + dedup append ----------
// Grid 148 blocks of 1024 (single wave, 1 block/SM by smem):
//   bid <  128 : walk + KNN (b = bid>>5, m0 = bid&31)
//   bid >= 128 : 20 prep blocks — zero scratch + w5 tile-transpose into g_w5t.
// Prep finishes in ~2us; walk blocks reach the flag-append phase only after
// staging + full walk (>=12us), so wave-1 co-residency makes this race-free.
__global__ __launch_bounds__(1024) void fpsknn_kernel(const float* __restrict__ x,
                                                      const int* __restrict__ far_init,
                                                      const float* __restrict__ w5) {
    extern __shared__ float dsm[];
    const int t = threadIdx.x;

    if (blockIdx.x >= BB * 32) {
        // ---- prep role ----
        const int blk = blockIdx.x - BB * 32;            // 0..19
        {   // zeroing: 20480 threads cover 2048 + 4096 + 4 words
            const int i = blk * 1024 + t;
            if (i < BB * NN / 32) ((unsigned*)g_flagbits)[i] = 0u;
            else if (i < BB * NN / 32 + BB * 1024) g_feat[i - BB * NN / 32] = 0.0f;
            else if (i < BB * NN / 32 + BB * 1024 + BB) g_list_cnt[i - BB * NN / 32 - BB * 1024] = 0;
        }
        // w5 transpose: 128 tiles of 32x32; 4 sub-groups of 256 threads per block
        const int sub = t >> 8, st = t & 255;
        const int tx = st & 31, ty = st >> 5;            // 8 rows per pass
        float* tile = dsm + sub * 1056;                  // 32x33
        #pragma unroll
        for (int round = 0; round < 2; ++round) {
            const int tl = blk * 4 + sub + round * 80;
            if (tl < 128) {
                const int k0 = (tl & 3) * 32, o0 = (tl >> 2) * 32;
                #pragma unroll
                for (int r = ty; r < 32; r += 8)
                    tile[r * 33 + tx] = w5[(o0 + r) * 128 + k0 + tx];
            }
            __syncthreads();
            if (tl < 128) {
                const int k0 = (tl & 3) * 32, o0 = (tl >> 2) * 32;
                #pragma unroll
                for (int r = ty; r < 32; r += 8)
                    g_w5t[(k0 + r) * 1024 + o0 + tx] = tile[tx * 33 + r];
            }
            __syncthreads();
        }
        return;
    }

    // ---- walk + KNN role ----
    float* sx = dsm;
    float* sy = sx + NN;
    float* sz = sy + NN;
    unsigned long long* cand = (unsigned long long*)(sz + NN);
    __shared__ unsigned s_du[2][32];
    __shared__ unsigned s_iu[2][32];
    __shared__ int s_cent[NC];
    __shared__ int s_stop;
    __shared__ unsigned s_minidx;

    const int b = blockIdx.x >> 5, m0 = blockIdx.x & 31;
    const float* xb = x + (size_t)b * NN * 3;
    const int w = t >> 5, lane = t & 31;
    const unsigned lmask_lt = (1u << lane) - 1u;

    // stage into smem SoA and adjacent-pair packed registers (R15-proven)
    unsigned long long prx[8], pry[8], prz[8];
    #pragma unroll
    for (int j = 0; j < 8; ++j) {
        const int i0 = t + (2 * j) * 1024, i1 = t + (2 * j + 1) * 1024;
        float a0 = xb[i0 * 3 + 0], b0 = xb[i0 * 3 + 1], c0 = xb[i0 * 3 + 2];
        float a1 = xb[i1 * 3 + 0], b1 = xb[i1 * 3 + 1], c1 = xb[i1 * 3 + 2];
        sx[i0] = a0; sy[i0] = b0; sz[i0] = c0;
        sx[i1] = a1; sy[i1] = b1; sz[i1] = c1;
        prx[j] = pack2(a0, a1); pry[j] = pack2(b0, b1); prz[j] = pack2(c0, c1);
    }
    if (t == 0) s_stop = 0;
    __syncthreads();

    // ---- FPS walk: packed distances, per-thread seen bits, 1 BAR/iter ----
    int far = far_init[b];
    int cnt = 0;
    unsigned myseen = 0;                 // thread t owns points t + j*1024 (bit j)
    for (int it = 0; it < NC; ++it) {
        if (t == (far & 1023)) {         // owner thread: cycle check + append
            const unsigned bt2 = 1u << (far >> 10);
            if (myseen & bt2) s_stop = 1;
            else { myseen |= bt2; s_cent[cnt] = far; }
        }
        const int pb = it & 1;
        const float cx = sx[far], cy = sy[far], cz = sz[far];
        const unsigned long long ncx = pack2(-cx, -cx);
        const unsigned long long ncy = pack2(-cy, -cy);
        const unsigned long long ncz = pack2(-cz, -cz);

        float best = -1.0f; int bi = 0;
        #pragma unroll
        for (int j = 0; j < 8; ++j) {
            unsigned long long dx2 = add2(prx[j], ncx);
            unsigned long long dy2 = add2(pry[j], ncy);
            unsigned long long dz2 = add2(prz[j], ncz);
            unsigned long long dd = mul2(dx2, dx2);
            ffma2(dd, dy2, dy2);
            ffma2(dd, dz2, dz2);
            float d0, d1; unpack2(dd, d0, d1);
            if (d0 > best) { best = d0; bi = t + (2 * j) * 1024; }       // ascending idx
            if (d1 > best) { best = d1; bi = t + (2 * j + 1) * 1024; }   // order preserved
        }
        const unsigned db = __float_as_uint(best);
        const unsigned dmax = __reduce_max_sync(0xffffffffu, db);
        const unsigned im = (db == dmax) ? (unsigned)bi : 0xffffffffu;
        const unsigned imin = __reduce_min_sync(0xffffffffu, im);
        if (lane == 0) { s_du[pb][w] = dmax; s_iu[pb][w] = imin; }
        __syncthreads();                 // publishes s_stop, s_du/s_iu
        if (s_stop) break;
        cnt++;
        if (it == NC - 1) break;
        const unsigned d2v = s_du[pb][lane];
        const unsigned i2v = s_iu[pb][lane];
        const unsigned dm2 = __reduce_max_sync(0xffffffffu, d2v);
        const unsigned ii = (d2v == dm2) ? i2v : 0xffffffffu;
        far = (int)__reduce_min_sync(0xffffffffu, ii);
    }
    __syncthreads();

    // ---- exact top-32 KNN via two-level radix select ----
    for (int m = m0; m < cnt; m += 32) {
        const int ci = s_cent[m];
        const float cx = sx[ci], cy = sy[ci], cz = sz[ci];
        const float cn = cx * cx + cy * cy + cz * cz;
        const int base = w * 512;

        unsigned ds[16];
        #pragma unroll
        for (int j = 0; j < 16; ++j) {
            const int p = base + j * 32 + lane;
            float px = sx[p], py = sy[p], pz = sz[p];
            float xn = px * px + py * py + pz * pz;
            float dot = cx * px + cy * py + cz * pz;
            ds[j] = sortable((cn + xn) - 2.0f * dot);
        }

        unsigned pfx = 0; int kth = 32;
        for (int bit = 31; bit >= 0; --bit) {
            const unsigned tgt = pfx << 1;
            int c = 0;
            #pragma unroll
            for (int j = 0; j < 16; ++j) c += ((ds[j] >> bit) == tgt);
            const int tot = __reduce_add_sync(0xffffffffu, c);
            if (kth <= tot) pfx = tgt; else { kth -= tot; pfx = tgt + 1; }
        }
        const unsigned T = pfx;

        unsigned selbits = 0;
        int cl = 0;
        #pragma unroll
        for (int j = 0; j < 16; ++j) {
            if (ds[j] < T) { selbits |= 1u << j; ++cl; }
        }
        int mtake = 32 - __reduce_add_sync(0xffffffffu, cl);
        while (mtake > 0) {
            unsigned me = 0xffffffffu; int jmin = -1;
            #pragma unroll
            for (int j = 0; j < 16; ++j) {
                if (ds[j] == T && !((selbits >> j) & 1u)) {
                    unsigned pid = (unsigned)(base + j * 32 + lane);
                    if (pid < me) { me = pid; jmin = j; }
                }
            }
            const unsigned gmin = __reduce_min_sync(0xffffffffu, me);
            if (me == gmin && jmin >= 0) selbits |= 1u << jmin;
            --mtake;
        }

        int off = 0;
        #pragma unroll
        for (int j = 0; j < 16; ++j) {
            const bool s = (selbits >> j) & 1u;
            const unsigned msk = __ballot_sync(0xffffffffu, s);
            if (s) {
                const int pos = off + __popc(msk & lmask_lt);
                cand[w * 32 + pos] = ((unsigned long long)ds[j] << 32)
                                   | (unsigned)(base + j * 32 + lane);
            }
            off += __popc(msk);
        }
        __syncthreads();

        const unsigned long long ck = cand[t];
        const unsigned cd = (unsigned)(ck >> 32);
        const unsigned cidx = (unsigned)ck;
        unsigned qfx = 0; int kb = 32;
        for (int bit = 31; bit >= 0; --bit) {
            const unsigned tgt = qfx << 1;
            const int c1 = __syncthreads_count((cd >> bit) == tgt);
            if (kb <= c1) qfx = tgt; else { kb -= c1; qfx = tgt + 1; }
        }
        const unsigned Tb = qfx;
        const int Lb = __syncthreads_count(cd < Tb);
        int mtk = 32 - Lb;
        bool takeme = (cd < Tb);
        while (mtk > 0) {
            if (t == 0) s_minidx = 0xffffffffu;
            __syncthreads();
            if (cd == Tb && !takeme) atomicMin(&s_minidx, cidx);
            __syncthreads();
            if (cd == Tb && !takeme && cidx == s_minidx) takeme = true;
            --mtk;
            __syncthreads();
        }
        if (takeme) {
            const int n = (int)cidx;
            const unsigned bt2 = 1u << (n & 31);
            unsigned old = atomicOr(&g_flagbits[b][(unsigned)n >> 5], bt2);
            if (!(old & bt2)) {
                int pos = atomicAdd(&g_list_cnt[b], 1);
                g_list[b][pos] = n;
            }
        }
        __syncthreads();
    }
}

// ---------------- fused chain+pool: layered output-parallel MLP + maxpool (R15) ---
#define PT 16
__global__ __launch_bounds__(512) void poolchain_kernel(
    const float* __restrict__ x,
    const float* __restrict__ w1, const float* __restrict__ b1,
    const float* __restrict__ w2, const float* __restrict__ b2,
    const float* __restrict__ w3, const float* __restrict__ b3,
    const float* __restrict__ w4, const float* __restrict__ b4,
    const float* __restrict__ b5) {
    extern __shared__ float psm[];
    float* hs  = psm;                    // [128][PT] k-major
    float* wA  = psm + 128 * PT;         // [64][68]
    float* wB  = wA + 64 * 68;           // [64][68]
    float* wC  = wB + 64 * 68;           // [128][68]
    float* h0  = wC + 128 * 68;          // [16][64]
    float* h1  = h0 + 16 * 64;           // [16][64]
    float* pts = h1 + 16 * 64;           // [16][4]

    const int bid = blockIdx.x;
    const int b = bid >> 5, q = (bid >> 3) & 3, slot = bid & 7;
    const int t = threadIdx.x;
    const int o = t & 63, pg = t >> 6;           // 8 groups x 2 points
    const int p0 = pg * 2, p1 = p0 + 1;

    for (int i = t; i < 64 * 64; i += 512) {
        const int r = i >> 6, c = i & 63;
        wA[r * 68 + c] = w2[i];
        wB[r * 68 + c] = w3[i];
    }
    for (int i = t; i < 128 * 64; i += 512) {
        const int r = i >> 6, c = i & 63;
        wC[r * 68 + c] = w4[i];
    }

    const int cnt = g_list_cnt[b];
    const int oo = q * 256 + (t & 255);
    const float bias = b5[oo];
    float rmax = 0.0f;

    for (int i0 = slot * PT; i0 < cnt; i0 += 8 * PT) {
        const int rem = min(PT, cnt - i0);
        __syncthreads();                 // weights staged / hs consumed
        if (t < PT) {
            if (t < rem) {
                const int n = g_list[b][i0 + t];
                const float* pp = x + ((size_t)b * NN + n) * 3;
                pts[t * 4 + 0] = pp[0]; pts[t * 4 + 1] = pp[1]; pts[t * 4 + 2] = pp[2];
            } else {
                pts[t * 4 + 0] = 0.f; pts[t * 4 + 1] = 0.f; pts[t * 4 + 2] = 0.f;
            }
        }
        __syncthreads();
        // L1: 3 -> 64
        {
            const float wa = w1[o * 3 + 0], wb = w1[o * 3 + 1], wc = w1[o * 3 + 2];
            const float bb = b1[o];
            float vA = bb + wa * pts[p0 * 4] + wb * pts[p0 * 4 + 1] + wc * pts[p0 * 4 + 2];
            float vB = bb + wa * pts[p1 * 4] + wb * pts[p1 * 4 + 1] + wc * pts[p1 * 4 + 2];
            h0[p0 * 64 + o] = fmaxf(vA, 0.f);
            h0[p1 * 64 + o] = fmaxf(vB, 0.f);
        }
        __syncthreads();
        // L2: 64 -> 64 (wA), h0 -> h1
        {
            const float4* wr = (const float4*)(wA + o * 68);
            const float4* hA = (const float4*)(h0 + p0 * 64);
            const float4* hB = (const float4*)(h0 + p1 * 64);
            float A0=0,A1=0,A2=0,A3=0,B0=0,B1=0,B2=0,B3=0;
            #pragma unroll
            for (int k = 0; k < 16; ++k) {
                float4 wf = wr[k], ha = hA[k], hb = hB[k];
                A0 += wf.x * ha.x; A1 += wf.y * ha.y; A2 += wf.z * ha.z; A3 += wf.w * ha.w;
                B0 += wf.x * hb.x; B1 += wf.y * hb.y; B2 += wf.z * hb.z; B3 += wf.w * hb.w;
            }
            const float bb = b2[o];
            h1[p0 * 64 + o] = fmaxf(bb + ((A0 + A1) + (A2 + A3)), 0.f);
            h1[p1 * 64 + o] = fmaxf(bb + ((B0 + B1) + (B2 + B3)), 0.f);
        }
        __syncthreads();
        // L3: 64 -> 64 (wB), h1 -> h0
        {
            const float4* wr = (const float4*)(wB + o * 68);
            const float4* hA = (const float4*)(h1 + p0 * 64);
            const float4* hB = (const float4*)(h1 + p1 * 64);
            float A0=0,A1=0,A2=0,A3=0,B0=0,B1=0,B2=0,B3=0;
            #pragma unroll
            for (int k = 0; k < 16; ++k) {
                float4 wf = wr[k], ha = hA[k], hb = hB[k];
                A0 += wf.x * ha.x; A1 += wf.y * ha.y; A2 += wf.z * ha.z; A3 += wf.w * ha.w;
                B0 += wf.x * hb.x; B1 += wf.y * hb.y; B2 += wf.z * hb.z; B3 += wf.w * hb.w;
            }
            const float bb = b3[o];
            h0[p0 * 64 + o] = fmaxf(bb + ((A0 + A1) + (A2 + A3)), 0.f);
            h0[p1 * 64 + o] = fmaxf(bb + ((B0 + B1) + (B2 + B3)), 0.f);
        }
        __syncthreads();
        // L4: 64 -> 128 (wC), h0 -> hs[ol][p]
        {
            #pragma unroll
            for (int j = 0; j < 2; ++j) {
                const int ol = o + 64 * j;
                const float4* wr = (const float4*)(wC + ol * 68);
                const float4* hA = (const float4*)(h0 + p0 * 64);
                const float4* hB = (const float4*)(h0 + p1 * 64);
                float A0=0,A1=0,A2=0,A3=0,B0=0,B1=0,B2=0,B3=0;
                #pragma unroll
                for (int k = 0; k < 16; ++k) {
                    float4 wf = wr[k], ha = hA[k], hb = hB[k];
                    A0 += wf.x * ha.x; A1 += wf.y * ha.y; A2 += wf.z * ha.z; A3 += wf.w * ha.w;
                    B0 += wf.x * hb.x; B1 += wf.y * hb.y; B2 += wf.z * hb.z; B3 += wf.w * hb.w;
                }
                const float bb = b4[ol];
                hs[ol * PT + p0] = (p0 < rem) ? fmaxf(bb + ((A0 + A1) + (A2 + A3)), 0.f) : 0.f;
                hs[ol * PT + p1] = (p1 < rem) ? fmaxf(bb + ((B0 + B1) + (B2 + B3)), 0.f) : 0.f;
            }
        }
        __syncthreads();

        // ---- pool phase: threads 0-255, packed f32x2, w5t coalesced from L2 ----
        if (t < 256) {
            unsigned long long acc2[8];
            #pragma unroll
            for (int pp = 0; pp < 8; ++pp) acc2[pp] = 0ull;

            const float* wtp = g_w5t + oo;
            #pragma unroll 4
            for (int k = 0; k < 128; ++k) {
                const float wv = wtp[k * 1024];
                unsigned long long wv2;
                asm("mov.b64 %0, {%1, %1};" : "=l"(wv2) : "r"(__float_as_uint(wv)));
                const float4* hp = (const float4*)(hs + k * PT);
                #pragma unroll
                for (int u = 0; u < 4; ++u) {
                    float4 h4v = hp[u];
                    unsigned long long lo, hi;
                    asm("mov.b64 %0, {%1, %2};" : "=l"(lo) : "r"(__float_as_uint(h4v.x)), "r"(__float_as_uint(h4v.y)));
                    asm("mov.b64 %0, {%1, %2};" : "=l"(hi) : "r"(__float_as_uint(h4v.z)), "r"(__float_as_uint(h4v.w)));
                    ffma2(acc2[2 * u],     wv2, lo);
                    ffma2(acc2[2 * u + 1], wv2, hi);
                }
            }
            for (int p = 0; p < rem; ++p) {
                const unsigned long long a = acc2[p >> 1];
                const float av = __uint_as_float((p & 1) ? (unsigned)(a >> 32) : (unsigned)a);
                rmax = fmaxf(rmax, fmaxf(av + bias, 0.0f));
            }
        }
    }

    if (t < 256)
        atomicMax((unsigned int*)&g_feat[b * 1024 + oo], __float_as_uint(rmax));
}

// ---------------- FC layer 1 (1024->512), one output per warp ---------------------
__global__ __launch_bounds__(256) void fc1_kernel(const float* __restrict__ fw1,
                                                  const float* __restrict__ fb1) {
    const int b = blockIdx.x >> 6, seg = blockIdx.x & 63;
    __shared__ __align__(16) float g[1024];
    const int t = threadIdx.x, w = t >> 5, lane = t & 31;

    for (int i = t; i < 1024; i += 256) g[i] = g_feat[b * 1024 + i];

    const int o = seg * 8 + w;
    const float4* wr = (const float4*)(fw1 + o * 1024);
    float4 wv[8];
    #pragma unroll
    for (int it = 0; it < 8; ++it) wv[it] = wr[it * 32 + lane];   // 8 LDGs in flight

    __syncthreads();
    float s = 0.0f;
    #pragma unroll
    for (int it = 0; it < 8; ++it) {
        float4 gv = *(const float4*)(g + it * 128 + lane * 4);
        s += wv[it].x * gv.x + wv[it].y * gv.y + wv[it].z * gv.z + wv[it].w * gv.w;
    }
    s = warp_sum(s);
    if (lane == 0) g_a1[b][o] = fmaxf(s + fb1[o], 0.0f);
}

// ---------------- FC layers 2+3 (512->256->3), 1 block per batch ------------------
__global__ __launch_bounds__(512) void fc2_kernel(
    const float* __restrict__ fw2, const float* __restrict__ fb2,
    const float* __restrict__ fw3, const float* __restrict__ fb3,
    float* __restrict__ out) {
    const int b = blockIdx.x;
    __shared__ __align__(16) float a1[512];
    __shared__ __align__(16) float a2[256];
    const int t = threadIdx.x, w = t >> 5, lane = t & 31;

    a1[t] = g_a1[b][t];
    __syncthreads();

    {
        const int o = w * 16;
        for (int j = 0; j < 16; ++j) {
            const float4* wr = (const float4*)(fw2 + (o + j) * 512);
            float s = 0.0f;
            #pragma unroll
            for (int it = 0; it < 4; ++it) {
                float4 wv = wr[it * 32 + lane];
                float4 av = *(const float4*)(a1 + it * 128 + lane * 4);
                s += wv.x * av.x + wv.y * av.y + wv.z * av.z + wv.w * av.w;
            }
            s = warp_sum(s);
            if (lane == 0) a2[o + j] = fmaxf(s + fb2[o + j], 0.0f);
        }
    }
    __syncthreads();

    if (w < 3) {
        const float4* wr = (const float4*)(fw3 + w * 256);
        float s = 0.0f;
        #pragma unroll
        for (int it = 0; it < 2; ++it) {
            float4 wv = wr[it * 32 + lane];
            float4 av = *(const float4*)(a2 + it * 128 + lane * 4);
            s += wv.x * av.x + wv.y * av.y + wv.z * av.z + wv.w * av.w;
        }
        s = warp_sum(s);
        if (lane == 0) out[b * 3 + w] = s + fb3[w];
    }
}

// ---------------- launch ----------------
extern "C" void kernel_launch(void* const* d_in, const int* in_sizes, int n_in,
                              void* d_out, int out_size) {
    const float* x   = (const float*)d_in[0];
    const int*   far = (const int*)  d_in[1];
    const float* w1 = (const float*)d_in[2];   const float* b1 = (const float*)d_in[3];
    const float* w2 = (const float*)d_in[4];   const float* b2 = (const float*)d_in[5];
    const float* w3 = (const float*)d_in[6];   const float* b3 = (const float*)d_in[7];
    const float* w4 = (const float*)d_in[8];   const float* b4 = (const float*)d_in[9];
    const float* w5 = (const float*)d_in[10];  const float* b5 = (const float*)d_in[11];
    const float* fw1 = (const float*)d_in[12]; const float* fb1 = (const float*)d_in[13];
    const float* fw2 = (const float*)d_in[14]; const float* fb2 = (const float*)d_in[15];
    const float* fw3 = (const float*)d_in[16]; const float* fb3 = (const float*)d_in[17];
    float* out = (float*)d_out;

    const int smem_fps  = 3 * NN * 4 + 1024 * 8;   // 204800
    const int smem_pool = (128 * PT + 64 * 68 * 2 + 128 * 68 + 16 * 64 * 2 + 16 * 4) * 4; // 86272
    static int attr_set = 0;
    if (!attr_set) {
        cudaFuncSetAttribute(fpsknn_kernel,
                             cudaFuncAttributeMaxDynamicSharedMemorySize, smem_fps);
        cudaFuncSetAttribute(poolchain_kernel,
                             cudaFuncAttributeMaxDynamicSharedMemorySize, smem_pool);
        attr_set = 1;
    }

    fpsknn_kernel<<<BB * 32 + 20, 1024, smem_fps>>>(x, far, w5);
    poolchain_kernel<<<BB * 32, 512, smem_pool>>>(x, w1, b1, w2, b2, w3, b3, w4, b4, b5);
    fc1_kernel<<<BB * 64, 256>>>(fw1, fb1);
    fc2_kernel<<<BB, 512>>>(fw2, fb2, fw3, fb3, out);
}